// round 9
// baseline (speedup 1.0000x reference)
#include <cuda_runtime.h>

// Problem constants (B=32, T=1024, N=2048)
#define BB 32
#define TT 1024
#define NN 2048
#define ALPHA 0.995f
#define VTH   2.0f

#define NCTA   1024          // persistent grid (all co-resident: 8/SM x 148)
#define ROWS_A 32            // gemv rows per CTA (32768 / 1024)
#define SEG    32            // grad T-segments (one per CTA per batch)
#define TSEG   (TT / SEG)    // 32 timesteps per grad segment

// Scratch (device globals -- no allocation allowed)
__device__ float g_S[BB * TT];   // S[b][t]
__device__ float g_A[BB * TT];   // a[b][t] = v_t + q_t
__device__ float g_V2[BB];       // sum v_t^2 per batch
__device__ unsigned g_bar1, g_bar2, g_scanflag;  // monotonic (replay-safe)

__global__ __launch_bounds__(128, 8) void k_fused(const float4* __restrict__ X4,
                                                  const float4* __restrict__ W4,
                                                  const float*  __restrict__ w,
                                                  float* __restrict__ out) {
    __shared__ float sv[TT];     // scan: s then v in place
    __shared__ float sa[TT];     // scan: a_t   (phase C reuses sa[0:TSEG])
    __shared__ float red[4];
    __shared__ float s_ww;
    __shared__ unsigned s_old1;

    const int tid = threadIdx.x;
    const int g   = blockIdx.x;

    // ================= Phase A: S[b,t] = x[b,t,:] . w =================
    const float4 w0 = W4[tid];
    const float4 w1 = W4[128 + tid];
    const float4 w2 = W4[256 + tid];
    const float4 w3 = W4[384 + tid];

    // zero the grad region of d_out (atomic targets for phase C);
    // 64 CTAs x 256 float4 = 16384 float4 = 65536 floats
    if (g < 64) {
        float4* gz = (float4*)(out + 2 * BB * TT) + g * 256;
        for (int i = tid; i < 256; i += 128)
            gz[i] = make_float4(0.f, 0.f, 0.f, 0.f);
    }

    const int base_row = g * ROWS_A;
#pragma unroll 1
    for (int rr = 0; rr < ROWS_A; rr++) {
        const int r = base_row + rr;                   // r = b*TT + t
        const float4* xp = X4 + (size_t)r * (NN / 4);
        const float4 x0 = xp[tid];
        const float4 x1 = xp[128 + tid];
        const float4 x2 = xp[256 + tid];
        const float4 x3 = xp[384 + tid];

        float s = x0.x * w0.x + x0.y * w0.y + x0.z * w0.z + x0.w * w0.w
                + x1.x * w1.x + x1.y * w1.y + x1.z * w1.z + x1.w * w1.w
                + x2.x * w2.x + x2.y * w2.y + x2.z * w2.z + x2.w * w2.w
                + x3.x * w3.x + x3.y * w3.y + x3.z * w3.z + x3.w * w3.w;

#pragma unroll
        for (int o = 16; o > 0; o >>= 1)
            s += __shfl_xor_sync(0xFFFFFFFFu, s, o);
        if ((tid & 31) == 0) red[tid >> 5] = s;
        __syncthreads();
        if (tid == 0) g_S[r] = red[0] + red[1] + red[2] + red[3];
        __syncthreads();
    }

    // ================= Grid barrier 1 (monotonic, replay-safe) =========
    if (tid == 0) {
        __threadfence();
        const unsigned old = atomicAdd(&g_bar1, 1u);
        s_old1 = old;
        const unsigned target = (old / NCTA + 1u) * NCTA;
        while (*(volatile unsigned*)&g_bar1 < target) __nanosleep(64);
        __threadfence();
    }
    __syncthreads();
    const unsigned launch_idx = s_old1 / NCTA;

    // ================= Phase B: scan (CTAs 0..31) | L2 prefetch ========
    const int b   = g >> 5;       // phase-C batch
    const int seg = g & 31;       // phase-C T-segment
    const int t0  = seg * TSEG;

    if (g < BB) {
        // ---- per-batch scalar scans, smem-resident ----
        const float* srow = g_S + g * TT;
        for (int t = tid; t < TT; t += 128) sv[t] = srow[t];

        if (tid < 32) {
            float ww = 0.0f;
#pragma unroll 8
            for (int i = tid; i < NN; i += 32) ww += w[i] * w[i];
#pragma unroll
            for (int o = 16; o > 0; o >>= 1)
                ww += __shfl_xor_sync(0xFFFFFFFFu, ww, o);
            if (tid == 0) s_ww = ww;
        }
        __syncthreads();

        if (tid == 0) {
            const float ww = s_ww;
            // forward: v_t = a*v + s_t - VTH*z_{t-1}  (pred-as-data select)
            float v = 0.0f, v2 = 0.0f;
#pragma unroll 8
            for (int t = 0; t < TT; t++) {
                const float s   = sv[t];
                const float sub = (v > VTH) ? VTH : 0.0f;
                v = fmaf(ALPHA, v, s) - sub;
                sv[t] = v;
                v2 += v * v;
            }
            g_V2[g] = v2;

            // backward: c_t reconstructed from v; q chain = single FFMA
            float q = 0.0f;
#pragma unroll 8
            for (int t = TT - 1; t > 0; t--) {
                const float vt = sv[t];
                const float vp = sv[t - 1];
                sa[t] = vt + q;
                const float zc = (vp > VTH) ? VTH : 0.0f;
                const float c  = vt - ALPHA * vp - vt * ww + zc;
                q = fmaf(ALPHA, q, c);
            }
            sa[0] = sv[0] + q;
        }
        __syncthreads();

        float* vout = out + g * TT;
        float* zout = out + BB * TT + g * TT;
        float* aout = g_A + g * TT;
        for (int t = tid; t < TT; t += 128) {
            const float v = sv[t];
            vout[t] = v;
            zout[t] = (v > VTH) ? 1.0f : 0.0f;
            aout[t] = sa[t];
        }
        if (tid == 0) { __threadfence(); atomicAdd(&g_scanflag, 1u); }
    } else {
        // ---- warm L2 with this CTA's own phase-C block; stop when scans done
        const unsigned scan_target = launch_idx * BB + BB;
        const char* base = (const char*)(X4 + ((size_t)b * TT + t0) * (NN / 4));
#pragma unroll 1
        for (int it = 0; it < 16; it++) {       // 16 x 16KB = full 256KB block
            const char* p = base + it * 16384 + tid * 128;
            asm volatile("prefetch.global.L2 [%0];" :: "l"(p));
            if (*(volatile unsigned*)&g_scanflag >= scan_target) break;
        }
    }

    // ================= Grid barrier 2 ==================================
    __syncthreads();
    if (tid == 0) {
        __threadfence();
        const unsigned old = atomicAdd(&g_bar2, 1u);
        const unsigned target = (old / NCTA + 1u) * NCTA;
        while (*(volatile unsigned*)&g_bar2 < target) __nanosleep(64);
        __threadfence();
    }
    __syncthreads();

    // ================= Phase C: grad += sum_t a_t * x_t ================
    if (tid < TSEG) sa[tid] = g_A[b * TT + t0 + tid];
    __syncthreads();

    const float4* xp = X4 + ((size_t)b * TT + t0) * (NN / 4);
    float4 a0 = make_float4(0.f, 0.f, 0.f, 0.f);
    float4 a1 = a0, a2 = a0, a3 = a0;
#pragma unroll 4
    for (int t = 0; t < TSEG; t++) {
        const float a = sa[t];
        const float4* row = xp + (size_t)t * (NN / 4);
        const float4 x0 = row[tid];
        const float4 x1 = row[128 + tid];
        const float4 x2 = row[256 + tid];
        const float4 x3 = row[384 + tid];
        a0.x += a * x0.x; a0.y += a * x0.y; a0.z += a * x0.z; a0.w += a * x0.w;
        a1.x += a * x1.x; a1.y += a * x1.y; a1.z += a * x1.z; a1.w += a * x1.w;
        a2.x += a * x2.x; a2.y += a * x2.y; a2.z += a * x2.z; a2.w += a * x2.w;
        a3.x += a * x3.x; a3.y += a * x3.y; a3.z += a * x3.z; a3.w += a * x3.w;
    }

    if (seg == 0) {  // fold -V2[b]*w[n] exactly once per (b,n)
        const float v2 = g_V2[b];
        const float4 wv0 = W4[tid];
        const float4 wv1 = W4[128 + tid];
        const float4 wv2 = W4[256 + tid];
        const float4 wv3 = W4[384 + tid];
        a0.x -= v2 * wv0.x; a0.y -= v2 * wv0.y; a0.z -= v2 * wv0.z; a0.w -= v2 * wv0.w;
        a1.x -= v2 * wv1.x; a1.y -= v2 * wv1.y; a1.z -= v2 * wv1.z; a1.w -= v2 * wv1.w;
        a2.x -= v2 * wv2.x; a2.y -= v2 * wv2.y; a2.z -= v2 * wv2.z; a2.w -= v2 * wv2.w;
        a3.x -= v2 * wv3.x; a3.y -= v2 * wv3.y; a3.z -= v2 * wv3.z; a3.w -= v2 * wv3.w;
    }

    float* gout = out + 2 * BB * TT + b * NN;
    atomicAdd(gout + 4 * tid + 0,        a0.x);
    atomicAdd(gout + 4 * tid + 1,        a0.y);
    atomicAdd(gout + 4 * tid + 2,        a0.z);
    atomicAdd(gout + 4 * tid + 3,        a0.w);
    atomicAdd(gout + 512 + 4 * tid + 0,  a1.x);
    atomicAdd(gout + 512 + 4 * tid + 1,  a1.y);
    atomicAdd(gout + 512 + 4 * tid + 2,  a1.z);
    atomicAdd(gout + 512 + 4 * tid + 3,  a1.w);
    atomicAdd(gout + 1024 + 4 * tid + 0, a2.x);
    atomicAdd(gout + 1024 + 4 * tid + 1, a2.y);
    atomicAdd(gout + 1024 + 4 * tid + 2, a2.z);
    atomicAdd(gout + 1024 + 4 * tid + 3, a2.w);
    atomicAdd(gout + 1536 + 4 * tid + 0, a3.x);
    atomicAdd(gout + 1536 + 4 * tid + 1, a3.y);
    atomicAdd(gout + 1536 + 4 * tid + 2, a3.z);
    atomicAdd(gout + 1536 + 4 * tid + 3, a3.w);
}

// ---------------------------------------------------------------------------
extern "C" void kernel_launch(void* const* d_in, const int* in_sizes, int n_in,
                              void* d_out, int out_size) {
    const float* x = (const float*)d_in[0];
    const float* w = (const float*)d_in[1];
    if (n_in >= 2 && in_sizes[0] == NN && in_sizes[1] != NN) {
        const float* tmp = x; x = w; w = tmp;
    }
    float* out = (float*)d_out;

    k_fused<<<NCTA, 128>>>((const float4*)x, (const float4*)w, w, out);
}

// round 10
// speedup vs baseline: 1.2168x; 1.2168x over previous
#include <cuda_runtime.h>

// Problem constants (B=32, T=1024, N=2048)
#define BB 32
#define TT 1024
#define NN 2048
#define ALPHA 0.995f
#define VTH   2.0f
#define SEG   16          // T-segments for k_grad_partial
#define TSEG  (TT / SEG)  // 64 timesteps per segment

#define SCAN_CTAS 1024    // k_scan grid: 32 scan + 992 prefetch CTAs
#define PF_ITERS  5       // per prefetch CTA: 5 x 16KB = 80KB; total ~77.5MB < L2

// Scratch (device globals -- no allocation allowed)
__device__ float g_S[BB * TT];   // S[b][t] = x[b,t,:] . w
__device__ float g_A[BB * TT];   // a[b][t] = v_t + q_t
__device__ float g_V2[BB];       // sum of v_t^2 per batch

// ---------------------------------------------------------------------------
// Kernel 1: S[b,t] = x[b,t,:] . w   (row dot products), [b][t] layout.
// grid = 4096 CTAs x 8 rows each, block = 128 threads, float4 loads.
// Measured ~6.15 TB/s -- at the read-stream HBM ceiling, unchanged.
// ---------------------------------------------------------------------------
__global__ __launch_bounds__(128) void k_gemv(const float4* __restrict__ X4,
                                              const float4* __restrict__ W4) {
    __shared__ float red[4];
    const int tid = threadIdx.x;

    const float4 w0 = W4[tid];
    const float4 w1 = W4[128 + tid];
    const float4 w2 = W4[256 + tid];
    const float4 w3 = W4[384 + tid];

    const int base_row = blockIdx.x * 8;

#pragma unroll 1
    for (int rr = 0; rr < 8; rr++) {
        const int r = base_row + rr;                 // r = b*TT + t
        const float4* xp = X4 + (size_t)r * (NN / 4);
        const float4 x0 = xp[tid];
        const float4 x1 = xp[128 + tid];
        const float4 x2 = xp[256 + tid];
        const float4 x3 = xp[384 + tid];

        float s = x0.x * w0.x + x0.y * w0.y + x0.z * w0.z + x0.w * w0.w
                + x1.x * w1.x + x1.y * w1.y + x1.z * w1.z + x1.w * w1.w
                + x2.x * w2.x + x2.y * w2.y + x2.z * w2.z + x2.w * w2.w
                + x3.x * w3.x + x3.y * w3.y + x3.z * w3.z + x3.w * w3.w;

#pragma unroll
        for (int o = 16; o > 0; o >>= 1)
            s += __shfl_xor_sync(0xFFFFFFFFu, s, o);
        if ((tid & 31) == 0) red[tid >> 5] = s;
        __syncthreads();
        if (tid == 0) g_S[r] = red[0] + red[1] + red[2] + red[3];
        __syncthreads();
    }
}

// ---------------------------------------------------------------------------
// Kernel 2: CTAs 0..31 run the per-batch scalar scans (smem-resident);
// CTAs 32..1023 prefetch a BOUNDED 77.5MB low-batch slice of X into L2
// for k_grad (complementary to what k_gemv's last wave leaves resident).
// Scan CTAs also zero the grad region of d_out (atomic targets).
// ---------------------------------------------------------------------------
__global__ __launch_bounds__(128) void k_scan(const float4* __restrict__ X4,
                                              const float* __restrict__ w,
                                              float* __restrict__ out) {
    __shared__ float sv[TT];   // holds s, then v in place
    __shared__ float sa[TT];   // a_t
    __shared__ float s_ww;
    const int tid = threadIdx.x;
    const int g   = blockIdx.x;

    if (g >= BB) {
        // ---- bounded L2 prefetch: CTA p covers 80KB starting at p*80KB ----
        const int p = g - BB;                       // 0..991
        const char* base = (const char*)X4 + (size_t)p * (PF_ITERS * 16384);
#pragma unroll
        for (int it = 0; it < PF_ITERS; it++) {
            const char* ptr = base + it * 16384 + tid * 128;
            asm volatile("prefetch.global.L2 [%0];" :: "l"(ptr));
        }
        return;
    }

    const int b = g;
    const float* srow = g_S + b * TT;
    for (int t = tid; t < TT; t += 128) sv[t] = srow[t];

    // zero this batch's grad slice (coalesced float4 stores)
    {
        float4* gz = (float4*)(out + 2 * BB * TT + b * NN);
#pragma unroll
        for (int i = tid; i < NN / 4; i += 128)
            gz[i] = make_float4(0.f, 0.f, 0.f, 0.f);
    }

    if (tid < 32) {
        float ww = 0.0f;
#pragma unroll 8
        for (int i = tid; i < NN; i += 32) ww += w[i] * w[i];
#pragma unroll
        for (int o = 16; o > 0; o >>= 1)
            ww += __shfl_xor_sync(0xFFFFFFFFu, ww, o);
        if (tid == 0) s_ww = ww;
    }
    __syncthreads();

    if (tid == 0) {
        const float ww = s_ww;

        // ---- forward scan: v_t = a*v_{t-1} + s_t - VTH*z_{t-1} ----
        float v = 0.0f, v2 = 0.0f;
#pragma unroll 8
        for (int t = 0; t < TT; t++) {
            const float s   = sv[t];
            const float sub = (v > VTH) ? VTH : 0.0f;  // pred-as-data FSEL
            v = fmaf(ALPHA, v, s) - sub;
            sv[t] = v;
            v2 += v * v;                               // off-chain
        }
        g_V2[b] = v2;

        // ---- backward scan: c_t reconstructed from v values ----
        float q = 0.0f;
#pragma unroll 8
        for (int t = TT - 1; t > 0; t--) {
            const float vt = sv[t];
            const float vp = sv[t - 1];
            sa[t] = vt + q;                                  // a_t = v_t + q_t
            const float zc = (vp > VTH) ? VTH : 0.0f;
            const float c  = vt - ALPHA * vp - vt * ww + zc; // off-chain
            q = fmaf(ALPHA, q, c);                           // 4cy FFMA chain
        }
        sa[0] = sv[0] + q;
    }
    __syncthreads();

    float* vout = out + b * TT;
    float* zout = out + BB * TT + b * TT;
    float* aout = g_A + b * TT;
    for (int t = tid; t < TT; t += 128) {
        const float v = sv[t];
        vout[t] = v;
        zout[t] = (v > VTH) ? 1.0f : 0.0f;
        aout[t] = sa[t];
    }
}

// ---------------------------------------------------------------------------
// Kernel 3: partial grad over a T-segment, accumulated into d_out via RED.
//   grad[b][n] += sum_{t in seg} a[b,t] * x[b,t,n]   (- V2[b]*w[n] on seg 0)
// grid = (4 chunks, 32 b, SEG) = 2048 CTAs, block = 128 threads.
// Per-row footprint per CTA: 128 threads x 16B = 2048 B contiguous.
// ---------------------------------------------------------------------------
__global__ __launch_bounds__(128) void k_grad_partial(const float4* __restrict__ X4,
                                                      const float4* __restrict__ W4,
                                                      float* __restrict__ out) {
    __shared__ float sa[TSEG];
    const int tid   = threadIdx.x;   // 0..127
    const int chunk = blockIdx.x;    // 0..3
    const int b     = blockIdx.y;    // 0..31
    const int seg   = blockIdx.z;    // 0..SEG-1
    const int t0    = seg * TSEG;

    if (tid < TSEG) sa[tid] = g_A[b * TT + t0 + tid];
    __syncthreads();

    const int col4 = chunk * 128 + tid;  // float4 column index, 0..511
    const float4* xp = X4 + ((size_t)b * TT + t0) * (NN / 4) + col4;

    float4 acc = make_float4(0.f, 0.f, 0.f, 0.f);
#pragma unroll 8
    for (int t = 0; t < TSEG; t++) {
        const float a = sa[t];
        const float4 x = xp[(size_t)t * (NN / 4)];
        acc.x += a * x.x;
        acc.y += a * x.y;
        acc.z += a * x.z;
        acc.w += a * x.w;
    }

    if (seg == 0) {  // fold in -V2[b]*w[n] exactly once
        const float v2 = g_V2[b];
        const float4 wv = W4[col4];
        acc.x -= v2 * wv.x;
        acc.y -= v2 * wv.y;
        acc.z -= v2 * wv.z;
        acc.w -= v2 * wv.w;
    }

    float* gout = out + 2 * BB * TT + b * NN + col4 * 4;
    atomicAdd(gout + 0, acc.x);   // RED.E.ADD.F32 (no return)
    atomicAdd(gout + 1, acc.y);
    atomicAdd(gout + 2, acc.z);
    atomicAdd(gout + 3, acc.w);
}

// ---------------------------------------------------------------------------
extern "C" void kernel_launch(void* const* d_in, const int* in_sizes, int n_in,
                              void* d_out, int out_size) {
    const float* x = (const float*)d_in[0];
    const float* w = (const float*)d_in[1];
    if (n_in >= 2 && in_sizes[0] == NN && in_sizes[1] != NN) {
        const float* tmp = x; x = w; w = tmp;
    }
    float* out = (float*)d_out;

    k_gemv<<<4096, 128>>>((const float4*)x, (const float4*)w);
    k_scan<<<SCAN_CTAS, 128>>>((const float4*)x, w, out);
    k_grad_partial<<<dim3(4, 32, SEG), 128>>>((const float4*)x, (const float4*)w, out);
}

// round 11
// speedup vs baseline: 1.2209x; 1.0033x over previous
#include <cuda_runtime.h>

// Problem constants (B=32, T=1024, N=2048)
#define BB 32
#define TT 1024
#define NN 2048
#define ALPHA 0.995f
#define VTH   2.0f
#define SEG   16          // T-segments for k_grad_partial
#define TSEG  (TT / SEG)  // 64 timesteps per segment

#define SCAN_CTAS 1024    // k_scan grid: 32 scan + 992 prefetch CTAs
#define PF_ITERS  5       // per prefetch CTA: 5 x 16KB = 80KB; total ~77.5MB < L2

// Scratch (device globals -- no allocation allowed)
__device__ float g_S[BB * TT];   // S[b][t] = x[b,t,:] . w
__device__ float g_A[BB * TT];   // a[b][t] = v_t + q_t
__device__ float g_V2[BB];       // sum of v_t^2 per batch

// ---------------------------------------------------------------------------
// Kernel 1: S[b,t] = x[b,t,:] . w   (row dot products), [b][t] layout.
// grid = 4096 CTAs x 8 rows each, block = 128 threads, float4 loads.
// Measured ~6.15 TB/s -- at the read-stream HBM ceiling, unchanged.
// ---------------------------------------------------------------------------
__global__ __launch_bounds__(128) void k_gemv(const float4* __restrict__ X4,
                                              const float4* __restrict__ W4) {
    __shared__ float red[4];
    const int tid = threadIdx.x;

    const float4 w0 = W4[tid];
    const float4 w1 = W4[128 + tid];
    const float4 w2 = W4[256 + tid];
    const float4 w3 = W4[384 + tid];

    const int base_row = blockIdx.x * 8;

#pragma unroll 1
    for (int rr = 0; rr < 8; rr++) {
        const int r = base_row + rr;                 // r = b*TT + t
        const float4* xp = X4 + (size_t)r * (NN / 4);
        const float4 x0 = xp[tid];
        const float4 x1 = xp[128 + tid];
        const float4 x2 = xp[256 + tid];
        const float4 x3 = xp[384 + tid];

        float s = x0.x * w0.x + x0.y * w0.y + x0.z * w0.z + x0.w * w0.w
                + x1.x * w1.x + x1.y * w1.y + x1.z * w1.z + x1.w * w1.w
                + x2.x * w2.x + x2.y * w2.y + x2.z * w2.z + x2.w * w2.w
                + x3.x * w3.x + x3.y * w3.y + x3.z * w3.z + x3.w * w3.w;

#pragma unroll
        for (int o = 16; o > 0; o >>= 1)
            s += __shfl_xor_sync(0xFFFFFFFFu, s, o);
        if ((tid & 31) == 0) red[tid >> 5] = s;
        __syncthreads();
        if (tid == 0) g_S[r] = red[0] + red[1] + red[2] + red[3];
        __syncthreads();
    }
}

// ---------------------------------------------------------------------------
// Kernel 2: CTAs 0..31 run the per-batch scalar scans (smem-resident);
// CTAs 32..1023 prefetch a BOUNDED 77.5MB low-batch slice of X into L2
// for k_grad (complementary to what k_gemv's last wave leaves resident).
// Scan CTAs also zero the grad region of d_out (atomic targets).
// ---------------------------------------------------------------------------
__global__ __launch_bounds__(128) void k_scan(const float4* __restrict__ X4,
                                              const float* __restrict__ w,
                                              float* __restrict__ out) {
    __shared__ float sv[TT];   // holds s, then v in place
    __shared__ float sa[TT];   // a_t
    __shared__ float s_ww;
    const int tid = threadIdx.x;
    const int g   = blockIdx.x;

    if (g >= BB) {
        // ---- bounded L2 prefetch: CTA p covers 80KB starting at p*80KB ----
        const int p = g - BB;                       // 0..991
        const char* base = (const char*)X4 + (size_t)p * (PF_ITERS * 16384);
#pragma unroll
        for (int it = 0; it < PF_ITERS; it++) {
            const char* ptr = base + it * 16384 + tid * 128;
            asm volatile("prefetch.global.L2 [%0];" :: "l"(ptr));
        }
        return;
    }

    const int b = g;
    const float* srow = g_S + b * TT;
    for (int t = tid; t < TT; t += 128) sv[t] = srow[t];

    // zero this batch's grad slice (coalesced float4 stores)
    {
        float4* gz = (float4*)(out + 2 * BB * TT + b * NN);
#pragma unroll
        for (int i = tid; i < NN / 4; i += 128)
            gz[i] = make_float4(0.f, 0.f, 0.f, 0.f);
    }

    if (tid < 32) {
        float ww = 0.0f;
#pragma unroll 8
        for (int i = tid; i < NN; i += 32) ww += w[i] * w[i];
#pragma unroll
        for (int o = 16; o > 0; o >>= 1)
            ww += __shfl_xor_sync(0xFFFFFFFFu, ww, o);
        if (tid == 0) s_ww = ww;
    }
    __syncthreads();

    if (tid == 0) {
        const float ww = s_ww;

        // ---- forward scan: v_t = a*v_{t-1} + s_t - VTH*z_{t-1} ----
        float v = 0.0f, v2 = 0.0f;
#pragma unroll 8
        for (int t = 0; t < TT; t++) {
            const float s   = sv[t];
            const float sub = (v > VTH) ? VTH : 0.0f;  // pred-as-data FSEL
            v = fmaf(ALPHA, v, s) - sub;
            sv[t] = v;
            v2 += v * v;                               // off-chain
        }
        g_V2[b] = v2;

        // ---- backward scan: c_t reconstructed from v values ----
        float q = 0.0f;
#pragma unroll 8
        for (int t = TT - 1; t > 0; t--) {
            const float vt = sv[t];
            const float vp = sv[t - 1];
            sa[t] = vt + q;                                  // a_t = v_t + q_t
            const float zc = (vp > VTH) ? VTH : 0.0f;
            const float c  = vt - ALPHA * vp - vt * ww + zc; // off-chain
            q = fmaf(ALPHA, q, c);                           // 4cy FFMA chain
        }
        sa[0] = sv[0] + q;
    }
    __syncthreads();

    float* vout = out + b * TT;
    float* zout = out + BB * TT + b * TT;
    float* aout = g_A + b * TT;
    for (int t = tid; t < TT; t += 128) {
        const float v = sv[t];
        vout[t] = v;
        zout[t] = (v > VTH) ? 1.0f : 0.0f;
        aout[t] = sa[t];
    }
}

// ---------------------------------------------------------------------------
// Kernel 3: partial grad over a T-segment, accumulated into d_out via RED.
//   grad[b][n] += sum_{t in seg} a[b,t] * x[b,t,n]   (- V2[b]*w[n] on seg 0)
// grid = (4 chunks, 32 b, SEG) = 2048 CTAs, block = 128 threads.
// Per-row footprint per CTA: 128 threads x 16B = 2048 B contiguous.
// ---------------------------------------------------------------------------
__global__ __launch_bounds__(128) void k_grad_partial(const float4* __restrict__ X4,
                                                      const float4* __restrict__ W4,
                                                      float* __restrict__ out) {
    __shared__ float sa[TSEG];
    const int tid   = threadIdx.x;   // 0..127
    const int chunk = blockIdx.x;    // 0..3
    const int b     = blockIdx.y;    // 0..31
    const int seg   = blockIdx.z;    // 0..SEG-1
    const int t0    = seg * TSEG;

    if (tid < TSEG) sa[tid] = g_A[b * TT + t0 + tid];
    __syncthreads();

    const int col4 = chunk * 128 + tid;  // float4 column index, 0..511
    const float4* xp = X4 + ((size_t)b * TT + t0) * (NN / 4) + col4;

    float4 acc = make_float4(0.f, 0.f, 0.f, 0.f);
#pragma unroll 8
    for (int t = 0; t < TSEG; t++) {
        const float a = sa[t];
        const float4 x = xp[(size_t)t * (NN / 4)];
        acc.x += a * x.x;
        acc.y += a * x.y;
        acc.z += a * x.z;
        acc.w += a * x.w;
    }

    if (seg == 0) {  // fold in -V2[b]*w[n] exactly once
        const float v2 = g_V2[b];
        const float4 wv = W4[col4];
        acc.x -= v2 * wv.x;
        acc.y -= v2 * wv.y;
        acc.z -= v2 * wv.z;
        acc.w -= v2 * wv.w;
    }

    float* gout = out + 2 * BB * TT + b * NN + col4 * 4;
    atomicAdd(gout + 0, acc.x);   // RED.E.ADD.F32 (no return)
    atomicAdd(gout + 1, acc.y);
    atomicAdd(gout + 2, acc.z);
    atomicAdd(gout + 3, acc.w);
}

// ---------------------------------------------------------------------------
extern "C" void kernel_launch(void* const* d_in, const int* in_sizes, int n_in,
                              void* d_out, int out_size) {
    const float* x = (const float*)d_in[0];
    const float* w = (const float*)d_in[1];
    if (n_in >= 2 && in_sizes[0] == NN && in_sizes[1] != NN) {
        const float* tmp = x; x = w; w = tmp;
    }
    float* out = (float*)d_out;

    k_gemv<<<4096, 128>>>((const float4*)x, (const float4*)w);
    k_scan<<<SCAN_CTAS, 128>>>((const float4*)x, w, out);
    k_grad_partial<<<dim3(4, 32, SEG), 128>>>((const float4*)x, (const float4*)w, out);
}